// round 5
// baseline (speedup 1.0000x reference)
#include <cuda_runtime.h>
#include <cstdint>
#include <cstddef>

// Problem constants (fixed by the reference).
#define Bb   2
#define Hh   16
#define Ss   2048
#define Dd   64
#define TQ   16          // queries per CTA
#define TK   8           // keys per k-tile
#define NKT  (Ss / TK)   // 256 k-tiles
#define NTH  256         // 16 heads x 16 queries

typedef unsigned long long u64;

// Padded smem row layout for K/V tiles (conflict-free 16B broadcast loads).
#define ROWP      (TK * Dd + 4)        // 516 floats per head per buffer
#define KVBUF     (Hh * ROWP)          // 8256 floats per buffer
#define SSH_HSTR  (TQ * 9)             // 144: 9-stride kills the q*8 bank pattern

__device__ __forceinline__ void ffma2(u64& acc, u64 a, u64 b) {
    asm volatile("fma.rn.f32x2 %0, %1, %2, %0;" : "+l"(acc) : "l"(a), "l"(b));
}
__device__ __forceinline__ u64 pack2(float lo, float hi) {
    u64 r; asm("mov.b64 %0, {%1,%2};" : "=l"(r) : "f"(lo), "f"(hi)); return r;
}
__device__ __forceinline__ void unpack2(u64 v, float& lo, float& hi) {
    asm("mov.b64 {%0,%1}, %2;" : "=f"(lo), "=f"(hi) : "l"(v));
}
__device__ __forceinline__ void cp16(float* sdst, const float* gsrc) {
    uint32_t sa = (uint32_t)__cvta_generic_to_shared(sdst);
    asm volatile("cp.async.cg.shared.global [%0], [%1], 16;" :: "r"(sa), "l"(gsrc));
}
__device__ __forceinline__ void cp_commit() { asm volatile("cp.async.commit_group;"); }
template <int N>
__device__ __forceinline__ void cp_wait() { asm volatile("cp.async.wait_group %0;" :: "n"(N)); }

__device__ __forceinline__ float neg_inf() { return __int_as_float(0xff800000); }

// ---------------------------------------------------------------------------
// Mask storage detection. The harness normalizes dtypes (bool is not a wire
// type), so mask_bool may arrive as int32 0/1, float32 0/1, bf16, or raw
// bytes. Only the ELEMENT SIZE matters downstream: "masked" == nonzero bits.
// ---------------------------------------------------------------------------
__device__ int g_mask_esz;   // 1, 2, or 4 bytes per mask element

#define F_BYTE_HI  1   // some nonzero bits in byte positions 1..3 of a word
#define F_NOT01B   2   // some byte not in {0,1}
#define F_NOTF32   4   // some word not in {0, 0x3f800000}
#define F_NOTBF16  8   // some 16-bit half not in {0, 0x3f80}

__global__ void detect_mask_kernel(const uint32_t* __restrict__ m, int nwords) {
    __shared__ int sflags;
    if (threadIdx.x == 0) sflags = 0;
    __syncthreads();
    int f = 0;
    for (int i = threadIdx.x; i < nwords; i += blockDim.x) {
        uint32_t w = m[i];
        if (w & 0xFFFFFF00u) f |= F_BYTE_HI;
        #pragma unroll
        for (int j = 0; j < 4; j++) {
            uint32_t byt = (w >> (8 * j)) & 0xffu;
            if (byt > 1u) f |= F_NOT01B;
        }
        if (w != 0u && w != 0x3f800000u) f |= F_NOTF32;
        uint32_t lo = w & 0xffffu, hi = w >> 16;
        if ((lo != 0u && lo != 0x3f80u) || (hi != 0u && hi != 0x3f80u)) f |= F_NOTBF16;
    }
    atomicOr(&sflags, f);
    __syncthreads();
    if (threadIdx.x == 0) {
        int ff = sflags;
        int esz;
        if (!(ff & F_BYTE_HI))      esz = 4;  // int32 0/1 (or all-zero; 4 is safe default)
        else if (!(ff & F_NOT01B))  esz = 1;  // byte-packed bool
        else if (!(ff & F_NOTF32))  esz = 4;  // float32 0.0/1.0 (nonzero-bit test works)
        else if (!(ff & F_NOTBF16)) esz = 2;  // bf16
        else                        esz = 1;  // fallback
        g_mask_esz = esz;
    }
}

// smem (floats): Kb[2*KVBUF] | Vb[2*KVBUF] | Ssh[16*144] | Msh[144] | Rsh[144]
#define SMEM_FLOATS (2 * KVBUF + 2 * KVBUF + Hh * SSH_HSTR + SSH_HSTR + SSH_HSTR)

__global__ void __launch_bounds__(NTH, 1)
attn_head_softmax_kernel(const float* __restrict__ Qg,
                         const float* __restrict__ Kg,
                         const float* __restrict__ Vg,
                         const unsigned char* __restrict__ Mg,
                         float* __restrict__ Og)
{
    extern __shared__ float smem[];
    float* Kb  = smem;                       // 2 * 8256
    float* Vb  = Kb + 2 * KVBUF;             // 2 * 8256
    float* Ssh = Vb + 2 * KVBUF;             // 16 * 144
    float* Msh = Ssh + Hh * SSH_HSTR;        // 144
    float* Rsh = Msh + SSH_HSTR;             // 144

    const int b  = blockIdx.y;
    const int q0 = blockIdx.x * TQ;
    const int t  = threadIdx.x;
    const int h  = t >> 4;     // 0..15
    const int q  = t & 15;     // 0..15

    const int esz = g_mask_esz;              // uniform

    // ---- Q row of this (h,q) into registers, pre-packed as f32x2 ----
    u64 Qp[32];
    {
        const ulonglong2* qg = reinterpret_cast<const ulonglong2*>(
            Qg + ((size_t)(b * Hh + h) * Ss + (q0 + q)) * Dd);
        #pragma unroll
        for (int i = 0; i < 16; i++) { ulonglong2 v = qg[i]; Qp[2*i] = v.x; Qp[2*i+1] = v.y; }
    }

    // ---- context accumulator (64 fp32 as 32 packed f32x2) ----
    u64 ctx[32];
    #pragma unroll
    for (int i = 0; i < 32; i++) ctx[i] = 0ull;

    // Mask row base in BYTES: element row stride is Ss, scaled by element size.
    const unsigned char* mrow =
        Mg + ((size_t)(b * Hh + h) * Ss + (q0 + q)) * (size_t)Ss * (size_t)esz;

    // ---- K/V tile loader: 2048 float4 per matrix, 8 per thread each ----
    auto load_tile = [&](int kt, int buf) {
        const int k0 = kt * TK;
        #pragma unroll
        for (int j = 0; j < 8; j++) {
            int i   = t + j * NTH;     // 0..2047
            int row = i >> 4;          // h2*TK + kk
            int d4  = i & 15;
            int h2  = row >> 3;
            int kk  = row & 7;
            size_t goff = ((size_t)(b * Hh + h2) * Ss + (k0 + kk)) * Dd + d4 * 4;
            int soff = buf * KVBUF + h2 * ROWP + kk * Dd + d4 * 4;
            cp16(&Kb[soff], Kg + goff);
            cp16(&Vb[soff], Vg + goff);
        }
    };

    load_tile(0, 0);
    cp_commit();

    for (int kt = 0; kt < NKT; kt++) {
        const int buf = kt & 1;
        if (kt + 1 < NKT) load_tile(kt + 1, (kt + 1) & 1);
        cp_commit();           // empty group on last iter is fine
        cp_wait<1>();          // tile kt is resident
        __syncthreads();       // (A) K/V visible to all threads

        const int k0 = kt * TK;

        // ---- 8 mask flags for keys k0..k0+7 (dtype-agnostic: nonzero bits) ----
        unsigned mk = 0;
        if (esz == 4) {
            const uint4* p = reinterpret_cast<const uint4*>(mrow + (size_t)k0 * 4);
            uint4 a = p[0], c = p[1];
            mk = (a.x ? 1u : 0u) | (a.y ? 2u : 0u) | (a.z ? 4u : 0u) | (a.w ? 8u : 0u)
               | (c.x ? 16u : 0u) | (c.y ? 32u : 0u) | (c.z ? 64u : 0u) | (c.w ? 128u : 0u);
        } else if (esz == 1) {
            u64 v = *reinterpret_cast<const u64*>(mrow + k0);
            #pragma unroll
            for (int j = 0; j < 8; j++)
                if ((v >> (8 * j)) & 0xffull) mk |= (1u << j);
        } else { // esz == 2
            uint4 a = *reinterpret_cast<const uint4*>(mrow + (size_t)k0 * 2);
            uint32_t w[4] = {a.x, a.y, a.z, a.w};
            #pragma unroll
            for (int j = 0; j < 4; j++) {
                if (w[j] & 0xffffu)   mk |= (1u << (2 * j));
                if (w[j] >> 16)       mk |= (1u << (2 * j + 1));
            }
        }

        // ---- scores: s[h][q][kk] = (Q . K) / 8, masked ----
        float sreg[TK];
        #pragma unroll
        for (int kk = 0; kk < TK; kk++) {
            const ulonglong2* kr = reinterpret_cast<const ulonglong2*>(
                &Kb[buf * KVBUF + h * ROWP + kk * Dd]);
            u64 acc = 0ull;
            #pragma unroll
            for (int i = 0; i < 16; i++) {
                ulonglong2 kv = kr[i];
                ffma2(acc, Qp[2*i],   kv.x);
                ffma2(acc, Qp[2*i+1], kv.y);
            }
            float lo, hi; unpack2(acc, lo, hi);
            float s = (lo + hi) * 0.125f;               // 1/sqrt(64)
            if ((mk >> kk) & 1u) s = neg_inf();
            sreg[kk] = s;
            Ssh[h * SSH_HSTR + q * 9 + kk] = s;
        }
        __syncthreads();       // (B) Ssh ready

        // ---- head softmax: 128 threads, one (q,kk) each, reduce over 16 h ----
        if (t < TQ * TK) {
            const int q2 = t >> 3, kk2 = t & 7;
            const int base = q2 * 9 + kk2;
            float m = neg_inf();
            #pragma unroll
            for (int h2 = 0; h2 < Hh; h2++) m = fmaxf(m, Ssh[h2 * SSH_HSTR + base]);
            float mm, inv;
            if (m == neg_inf()) { mm = 0.f; inv = 0.f; }   // all heads masked (never, per ref)
            else {
                float sum = 0.f;
                #pragma unroll
                for (int h2 = 0; h2 < Hh; h2++)
                    sum += __expf(Ssh[h2 * SSH_HSTR + base] - m);
                mm = m; inv = 1.0f / sum;
            }
            Msh[base] = mm;
            Rsh[base] = inv;
        }
        __syncthreads();       // (C) Msh/Rsh ready

        // ---- context accumulate: ctx += w * V ----
        #pragma unroll
        for (int kk = 0; kk < TK; kk++) {
            const int base = q * 9 + kk;
            float w = __expf(sreg[kk] - Msh[base]) * Rsh[base];
            u64 wp = pack2(w, w);
            const ulonglong2* vr = reinterpret_cast<const ulonglong2*>(
                &Vb[buf * KVBUF + h * ROWP + kk * Dd]);
            #pragma unroll
            for (int i = 0; i < 16; i++) {
                ulonglong2 vv = vr[i];
                ffma2(ctx[2*i],   wp, vv.x);
                ffma2(ctx[2*i+1], wp, vv.y);
            }
        }
        __syncthreads();       // (D) done with buf + Ssh before next prefetch/overwrite
    }

    // ---- epilogue: out[b, q0+q, h, :] = ctx (fp32, contiguous 256B per thread) ----
    ulonglong2* og = reinterpret_cast<ulonglong2*>(
        Og + ((size_t)(b * Ss + (q0 + q)) * Hh + h) * Dd);
    #pragma unroll
    for (int i = 0; i < 16; i++) {
        ulonglong2 v; v.x = ctx[2*i]; v.y = ctx[2*i+1];
        og[i] = v;
    }
}

extern "C" void kernel_launch(void* const* d_in, const int* in_sizes, int n_in,
                              void* d_out, int out_size) {
    const float*         Q = (const float*)d_in[0];
    const float*         K = (const float*)d_in[1];
    const float*         V = (const float*)d_in[2];
    const unsigned char* M = (const unsigned char*)d_in[3];   // mask, dtype detected on-device
    // d_in[4] = head_dim (compile-time 64); unused.
    float* O = (float*)d_out;

    // 1) classify mask storage (element size). 64K words = 256 KB sample,
    //    far below the minimum possible mask allocation (>=128 MB). Deterministic.
    detect_mask_kernel<<<1, 256>>>((const uint32_t*)M, 1 << 16);

    // 2) main attention kernel
    const size_t smem_bytes = (size_t)SMEM_FLOATS * sizeof(float);  // ~142 KB
    cudaFuncSetAttribute(attn_head_softmax_kernel,
                         cudaFuncAttributeMaxDynamicSharedMemorySize,
                         (int)smem_bytes);

    dim3 grid(Ss / TQ, Bb);   // (128, 2) = 256 CTAs
    attn_head_softmax_kernel<<<grid, NTH, smem_bytes>>>(Q, K, V, M, O);
}